// round 7
// baseline (speedup 1.0000x reference)
#include <cuda_runtime.h>
#include <cuda_pipeline.h>
#include <cstdint>

// GaussianVoxelizer: 2M gaussians -> 640K voxels argmax-by-opacity (min-index
// tiebreak), then per-voxel gather + analytic covariance inverse.
//
// Two kernels:
//  - scatter: per-gaussian atomicMax with key = (opa_bits << 32) | (~index).
//  - output: per-voxel decode key, reset g_keys[g]=0 (zero-invariant across
//      graph replays; device globals are zero-initialized at load), gather
//      the 21 passthrough floats global->smem via cp.async (LDGSTS): no
//      register destination means the allocator cannot serialize the gather
//      (rounds 4-6 lesson: ptxas chunks LDG->reg->STS at ~6 in flight; the
//      async copy engine keeps all 21 outstanding). Only scales+rots are
//      gathered into registers for the covinv math, which overlaps the
//      async copies. Rows staged in smem, written back coalesced float4.
//
// Voxel binning matches XLA's lowering of (x - vol_min) / 0.4: divide by
// constant folds to multiply by reciprocal; 1/0.4f == 2.5f exactly.

namespace {
constexpr int kH = 200, kW = 200, kD = 16;
constexpr int kV = kH * kW * kD;   // 640000
constexpr int kRow = 31;
constexpr int kBlk = 256;
}

__device__ unsigned long long g_keys[kV];   // zero-initialized at module load

__global__ void gv_scatter_kernel(const float* __restrict__ means,
                                  const float* __restrict__ opac,
                                  int n) {
    int i = blockIdx.x * blockDim.x + threadIdx.x;
    if (i >= n) return;
    float x = means[3 * i + 0];
    float y = means[3 * i + 1];
    float z = means[3 * i + 2];
    // Match XLA: (p - VOL_MIN) * (1/VOX) with 1/0.4f == 2.5f, round-half-even.
    int vx = __float2int_rn(__fmul_rn(__fadd_rn(x, 40.0f), 2.5f));
    int vy = __float2int_rn(__fmul_rn(__fadd_rn(y, 40.0f), 2.5f));
    int vz = __float2int_rn(__fmul_rn(__fadd_rn(z, 1.0f), 2.5f));
    vx = min(max(vx, 0), kH - 1);
    vy = min(max(vy, 0), kW - 1);
    vz = min(max(vz, 0), kD - 1);
    int flat = vx * (kW * kD) + vy * kD + vz;
    float o = opac[i];
    // opacity in [0,1) -> non-negative float, bit pattern is order-preserving.
    unsigned long long key =
        ((unsigned long long)__float_as_uint(o) << 32) |
        (unsigned long long)(0xFFFFFFFFu - (unsigned)i);
    atomicMax(&g_keys[flat], key);
}

__global__ void __launch_bounds__(kBlk)
gv_output_kernel(const float* __restrict__ means,
                 const float* __restrict__ opac,
                 const float* __restrict__ feats,
                 const float* __restrict__ scales,
                 const float* __restrict__ rots,
                 const float* __restrict__ empty_scalar,
                 float* __restrict__ out) {
    __shared__ float srows[kBlk * kRow];

    int tid = threadIdx.x;
    int g = blockIdx.x * kBlk + tid;
    float* row = srows + tid * kRow;   // stride 31 mod 32 -> conflict-free

    if (g <= kV) {
        float sx = 1.0f, sy = 1.0f, sz = 1.0f;
        float qw = 1.0f, qx = 0.0f, qy = 0.0f, qz = 0.0f;

        if (g == kV) {
            // appended "empty" gaussian row (constants, no gather)
            row[0] = 0.0f; row[1] = 0.0f; row[2] = 2.2f;
            row[3] = 1.0f;
#pragma unroll
            for (int c = 4; c < 21; c++) row[c] = 0.0f;
            row[21] = empty_scalar[0];       // EMPTY_LABEL semantic
            sx = 100.0f; sy = 100.0f; sz = 8.0f;
        } else {
            unsigned long long key = g_keys[g];
            g_keys[g] = 0ull;   // restore zero-invariant for next replay
            if (key != 0ull) {
                int idx = (int)(0xFFFFFFFFu - (unsigned)(key & 0xFFFFFFFFull));
                const float* pm = means + 3 * idx;
                const float* pf = feats + 17 * idx;

                // 21 async 4B gathers straight into the staging row:
                // zero register cost, all outstanding simultaneously.
                __pipeline_memcpy_async(&row[0], pm + 0, 4);
                __pipeline_memcpy_async(&row[1], pm + 1, 4);
                __pipeline_memcpy_async(&row[2], pm + 2, 4);
                __pipeline_memcpy_async(&row[3], opac + idx, 4);
#pragma unroll
                for (int c = 0; c < 17; c++)
                    __pipeline_memcpy_async(&row[4 + c], pf + c, 4);
                __pipeline_commit();

                row[21] = 0.0f;   // class-17 slot (distinct address, safe)

                // register gathers only for covinv inputs (7 floats)
                const float* ps = scales + 3 * idx;
                float4 q = *reinterpret_cast<const float4*>(rots + 4 * idx);
                sx = ps[0]; sy = ps[1]; sz = ps[2];
                qw = q.x; qx = q.y; qy = q.z; qz = q.w;
            } else {
                // invalid voxel: zeros + identity covinv (defaults)
#pragma unroll
                for (int c = 0; c < 22; c++) row[c] = 0.0f;
            }
        }

        // covinv math overlaps the in-flight async copies
        float nrm = sqrtf(qw * qw + qx * qx + qy * qy + qz * qz);
        float inv = 1.0f / nrm;
        qw *= inv; qx *= inv; qy *= inv; qz *= inv;

        float r00 = 1.0f - 2.0f * (qy * qy + qz * qz);
        float r01 = 2.0f * (qx * qy - qw * qz);
        float r02 = 2.0f * (qx * qz + qw * qy);
        float r10 = 2.0f * (qx * qy + qw * qz);
        float r11 = 1.0f - 2.0f * (qx * qx + qz * qz);
        float r12 = 2.0f * (qy * qz - qw * qx);
        float r20 = 2.0f * (qx * qz - qw * qy);
        float r21 = 2.0f * (qy * qz + qw * qx);
        float r22 = 1.0f - 2.0f * (qx * qx + qy * qy);

        // cov = R^T S^2 R  =>  cov_inv = R^T S^-2 R (analytic, symmetric)
        float a0 = 1.0f / (sx * sx);
        float a1 = 1.0f / (sy * sy);
        float a2 = 1.0f / (sz * sz);

        float c00 = r00 * r00 * a0 + r10 * r10 * a1 + r20 * r20 * a2;
        float c01 = r00 * r01 * a0 + r10 * r11 * a1 + r20 * r21 * a2;
        float c02 = r00 * r02 * a0 + r10 * r12 * a1 + r20 * r22 * a2;
        float c11 = r01 * r01 * a0 + r11 * r11 * a1 + r21 * r21 * a2;
        float c12 = r01 * r02 * a0 + r11 * r12 * a1 + r21 * r22 * a2;
        float c22 = r02 * r02 * a0 + r12 * r12 * a1 + r22 * r22 * a2;

        row[22] = c00; row[23] = c01; row[24] = c02;
        row[25] = c01; row[26] = c11; row[27] = c12;
        row[28] = c02; row[29] = c12; row[30] = c22;

        __pipeline_wait_prior(0);   // async gathers done before writeback
    }

    __syncthreads();

    // coalesced writeback: full blocks cover a contiguous span of
    // kBlk*31 floats (16B-aligned: 256*31*4 % 16 == 0) -> float4 path.
    int base = blockIdx.x * kBlk;
    int nrows = min(kBlk, kV + 1 - base);
    if (nrows <= 0) return;

    if (nrows == kBlk) {
        constexpr int kVec = kBlk * kRow / 4;   // 1984 float4s
        float4* po = reinterpret_cast<float4*>(out + (size_t)base * kRow);
        const float4* ps = reinterpret_cast<const float4*>(srows);
#pragma unroll 4
        for (int e = tid; e < kVec; e += kBlk) {
            po[e] = ps[e];
        }
    } else {
        int nelem = nrows * kRow;
        float* po = out + (size_t)base * kRow;
        for (int e = tid; e < nelem; e += kBlk) {
            po[e] = srows[e];
        }
    }
}

extern "C" void kernel_launch(void* const* d_in, const int* in_sizes, int n_in,
                              void* d_out, int out_size) {
    const float* means        = (const float*)d_in[0];  // [N,3]
    const float* opac         = (const float*)d_in[1];  // [N,1]
    const float* feats        = (const float*)d_in[2];  // [N,17]
    const float* scales       = (const float*)d_in[3];  // [N,3]
    const float* rots         = (const float*)d_in[4];  // [N,4]
    const float* empty_scalar = (const float*)d_in[5];  // [1]
    float* out = (float*)d_out;                         // [1, V+1, 31]

    int n = in_sizes[0] / 3;

    gv_scatter_kernel<<<(n + 255) / 256, 256>>>(means, opac, n);
    gv_output_kernel<<<(kV + 1 + kBlk - 1) / kBlk, kBlk>>>(
        means, opac, feats, scales, rots, empty_scalar, out);
}

// round 8
// speedup vs baseline: 1.9797x; 1.9797x over previous
#include <cuda_runtime.h>
#include <cstdint>

// GaussianVoxelizer: 2M gaussians -> 640K voxels argmax-by-opacity (min-index
// tiebreak), then per-voxel gather + analytic covariance inverse.
//
// Two kernels:
//  - scatter: per-gaussian atomicMax with key = (opa_bits << 32) | (~index).
//  - output: per-voxel decode key, reset g_keys[g]=0 (zero-invariant across
//      graph replays; device globals are zero-initialized at load), gather
//      attributes into the r[31] REGISTER ARRAY, compute R^T S^-2 R, copy
//      the array to smem, write back coalesced float4.
//
// CODEGEN-CRITICAL (rounds 3-7 evidence): the gather destinations must be
// elements of one local array that is copied to smem ONLY AT THE END. That
// keeps every gather LDG's destination register live until the copy, so
// ptxas issues all ~21 LDGs back-to-back (full MLP). Every restructuring
// tried (separate scalars + direct smem stores: 90us; cp.async 4B gathers:
// 192us) let the allocator serialize the gather and regressed. Do not
// "clean this up".
//
// Voxel binning matches XLA's lowering of (x - vol_min) / 0.4: divide by
// constant folds to multiply by reciprocal; 1/0.4f == 2.5f exactly.

namespace {
constexpr int kH = 200, kW = 200, kD = 16;
constexpr int kV = kH * kW * kD;   // 640000
constexpr int kRow = 31;
constexpr int kBlk = 256;
}

__device__ unsigned long long g_keys[kV];   // zero-initialized at module load

__global__ void gv_scatter_kernel(const float* __restrict__ means,
                                  const float* __restrict__ opac,
                                  int n) {
    int i = blockIdx.x * blockDim.x + threadIdx.x;
    if (i >= n) return;
    float x = means[3 * i + 0];
    float y = means[3 * i + 1];
    float z = means[3 * i + 2];
    // Match XLA: (p - VOL_MIN) * (1/VOX) with 1/0.4f == 2.5f, round-half-even.
    int vx = __float2int_rn(__fmul_rn(__fadd_rn(x, 40.0f), 2.5f));
    int vy = __float2int_rn(__fmul_rn(__fadd_rn(y, 40.0f), 2.5f));
    int vz = __float2int_rn(__fmul_rn(__fadd_rn(z, 1.0f), 2.5f));
    vx = min(max(vx, 0), kH - 1);
    vy = min(max(vy, 0), kW - 1);
    vz = min(max(vz, 0), kD - 1);
    int flat = vx * (kW * kD) + vy * kD + vz;
    float o = opac[i];
    // opacity in [0,1) -> non-negative float, bit pattern is order-preserving.
    unsigned long long key =
        ((unsigned long long)__float_as_uint(o) << 32) |
        (unsigned long long)(0xFFFFFFFFu - (unsigned)i);
    atomicMax(&g_keys[flat], key);
}

__global__ void __launch_bounds__(kBlk)
gv_output_kernel(const float* __restrict__ means,
                 const float* __restrict__ opac,
                 const float* __restrict__ feats,
                 const float* __restrict__ scales,
                 const float* __restrict__ rots,
                 const float* __restrict__ empty_scalar,
                 float* __restrict__ out) {
    __shared__ float srows[kBlk * kRow];

    int tid = threadIdx.x;
    int g = blockIdx.x * kBlk + tid;

    if (g <= kV) {
        float r[kRow];
#pragma unroll
        for (int c = 0; c < kRow; c++) r[c] = 0.0f;

        float sx = 1.0f, sy = 1.0f, sz = 1.0f;
        float qw = 1.0f, qx = 0.0f, qy = 0.0f, qz = 0.0f;

        if (g == kV) {
            // appended "empty" gaussian row
            r[2] = 2.2f;
            r[3] = 1.0f;                     // opacity
            r[4 + 17] = empty_scalar[0];     // EMPTY_LABEL semantic
            sx = 100.0f; sy = 100.0f; sz = 8.0f;
        } else {
            unsigned long long key = g_keys[g];
            g_keys[g] = 0ull;   // restore zero-invariant for next replay
            if (key != 0ull) {
                int idx = (int)(0xFFFFFFFFu - (unsigned)(key & 0xFFFFFFFFull));
                // all loads below are independent, destinations all live
                // until the final smem copy -> full MLP
                r[0] = means[3 * idx + 0];
                r[1] = means[3 * idx + 1];
                r[2] = means[3 * idx + 2];
                r[3] = opac[idx];
#pragma unroll
                for (int c = 0; c < 17; c++) r[4 + c] = feats[17 * idx + c];
                sx = scales[3 * idx + 0];
                sy = scales[3 * idx + 1];
                sz = scales[3 * idx + 2];
                float4 q = *reinterpret_cast<const float4*>(rots + 4 * idx);
                qw = q.x; qx = q.y; qy = q.z; qz = q.w;
            }
            // invalid voxel: defaults -> covinv = I, rest 0 (matches ref).
        }

        float nrm = sqrtf(qw * qw + qx * qx + qy * qy + qz * qz);
        float inv = 1.0f / nrm;
        qw *= inv; qx *= inv; qy *= inv; qz *= inv;

        float r00 = 1.0f - 2.0f * (qy * qy + qz * qz);
        float r01 = 2.0f * (qx * qy - qw * qz);
        float r02 = 2.0f * (qx * qz + qw * qy);
        float r10 = 2.0f * (qx * qy + qw * qz);
        float r11 = 1.0f - 2.0f * (qx * qx + qz * qz);
        float r12 = 2.0f * (qy * qz - qw * qx);
        float r20 = 2.0f * (qx * qz - qw * qy);
        float r21 = 2.0f * (qy * qz + qw * qx);
        float r22 = 1.0f - 2.0f * (qx * qx + qy * qy);

        // cov = R^T S^2 R  =>  cov_inv = R^T S^-2 R (analytic, symmetric)
        float a0 = 1.0f / (sx * sx);
        float a1 = 1.0f / (sy * sy);
        float a2 = 1.0f / (sz * sz);

        float c00 = r00 * r00 * a0 + r10 * r10 * a1 + r20 * r20 * a2;
        float c01 = r00 * r01 * a0 + r10 * r11 * a1 + r20 * r21 * a2;
        float c02 = r00 * r02 * a0 + r10 * r12 * a1 + r20 * r22 * a2;
        float c11 = r01 * r01 * a0 + r11 * r11 * a1 + r21 * r21 * a2;
        float c12 = r01 * r02 * a0 + r11 * r12 * a1 + r21 * r22 * a2;
        float c22 = r02 * r02 * a0 + r12 * r12 * a1 + r22 * r22 * a2;

        r[22] = c00; r[23] = c01; r[24] = c02;
        r[25] = c01; r[26] = c11; r[27] = c12;
        r[28] = c02; r[29] = c12; r[30] = c22;

        // stage row in smem: address tid*31 + c, stride 31 mod 32 ->
        // conflict-free for any fixed c.
#pragma unroll
        for (int c = 0; c < kRow; c++) srows[tid * kRow + c] = r[c];
    }

    __syncthreads();

    // coalesced writeback: full blocks cover a contiguous span of
    // kBlk*31 floats (16B-aligned: 256*31*4 % 16 == 0) -> float4 path.
    int base = blockIdx.x * kBlk;
    int nrows = min(kBlk, kV + 1 - base);
    if (nrows <= 0) return;

    if (nrows == kBlk) {
        constexpr int kVec = kBlk * kRow / 4;   // 1984 float4s
        float4* po = reinterpret_cast<float4*>(out + (size_t)base * kRow);
        const float4* ps = reinterpret_cast<const float4*>(srows);
#pragma unroll 4
        for (int e = tid; e < kVec; e += kBlk) {
            po[e] = ps[e];
        }
    } else {
        int nelem = nrows * kRow;
        float* po = out + (size_t)base * kRow;
        for (int e = tid; e < nelem; e += kBlk) {
            po[e] = srows[e];
        }
    }
}

extern "C" void kernel_launch(void* const* d_in, const int* in_sizes, int n_in,
                              void* d_out, int out_size) {
    const float* means        = (const float*)d_in[0];  // [N,3]
    const float* opac         = (const float*)d_in[1];  // [N,1]
    const float* feats        = (const float*)d_in[2];  // [N,17]
    const float* scales       = (const float*)d_in[3];  // [N,3]
    const float* rots         = (const float*)d_in[4];  // [N,4]
    const float* empty_scalar = (const float*)d_in[5];  // [1]
    float* out = (float*)d_out;                         // [1, V+1, 31]

    int n = in_sizes[0] / 3;

    gv_scatter_kernel<<<(n + 255) / 256, 256>>>(means, opac, n);
    gv_output_kernel<<<(kV + 1 + kBlk - 1) / kBlk, kBlk>>>(
        means, opac, feats, scales, rots, empty_scalar, out);
}

// round 9
// speedup vs baseline: 2.5952x; 1.3109x over previous
#include <cuda_runtime.h>
#include <cstdint>

// GaussianVoxelizer: 2M gaussians -> 640K voxels argmax-by-opacity (min-index
// tiebreak), then per-voxel gather + analytic covariance inverse.
//
// ROUND-3 EXACT STRUCTURE (78.3us baseline) + ONE delta: float4 writeback.
// Controlled bisect of the rounds-4..8 regression: every variant that added
// (a) g_keys reset inside output and/or (b) float4 rots load came out at
// output=89-90us / regs=48. Round 3 (init kernel, no reset, scalar rots)
// had output ~60us. Keep init kernel; keep scalar rots; NO reset store.
//
// CODEGEN-CRITICAL: gather destinations are elements of one r[31] local
// array copied to smem only at the end -> all gather LDGs stay live ->
// full MLP. Do not restructure (rounds 4-7 regressions).
//
// Voxel binning matches XLA's lowering of (x - vol_min) / 0.4: divide by
// constant folds to multiply by reciprocal; 1/0.4f == 2.5f exactly.

namespace {
constexpr int kH = 200, kW = 200, kD = 16;
constexpr int kV = kH * kW * kD;   // 640000
constexpr int kRow = 31;
constexpr int kBlk = 256;
}

__device__ unsigned long long g_keys[kV];

__global__ void gv_init_kernel() {
    int i = blockIdx.x * blockDim.x + threadIdx.x;
    ulonglong2* p = reinterpret_cast<ulonglong2*>(g_keys);
    if (i < kV / 2) p[i] = make_ulonglong2(0ull, 0ull);
}

__global__ void gv_scatter_kernel(const float* __restrict__ means,
                                  const float* __restrict__ opac,
                                  int n) {
    int i = blockIdx.x * blockDim.x + threadIdx.x;
    if (i >= n) return;
    float x = means[3 * i + 0];
    float y = means[3 * i + 1];
    float z = means[3 * i + 2];
    // Match XLA: (p - VOL_MIN) * (1/VOX) with 1/0.4f == 2.5f, round-half-even.
    int vx = __float2int_rn(__fmul_rn(__fadd_rn(x, 40.0f), 2.5f));
    int vy = __float2int_rn(__fmul_rn(__fadd_rn(y, 40.0f), 2.5f));
    int vz = __float2int_rn(__fmul_rn(__fadd_rn(z, 1.0f), 2.5f));
    vx = min(max(vx, 0), kH - 1);
    vy = min(max(vy, 0), kW - 1);
    vz = min(max(vz, 0), kD - 1);
    int flat = vx * (kW * kD) + vy * kD + vz;
    float o = opac[i];
    // opacity in [0,1) -> non-negative float, bit pattern is order-preserving.
    unsigned long long key =
        ((unsigned long long)__float_as_uint(o) << 32) |
        (unsigned long long)(0xFFFFFFFFu - (unsigned)i);
    atomicMax(&g_keys[flat], key);
}

__global__ void __launch_bounds__(kBlk)
gv_output_kernel(const float* __restrict__ means,
                 const float* __restrict__ opac,
                 const float* __restrict__ feats,
                 const float* __restrict__ scales,
                 const float* __restrict__ rots,
                 const float* __restrict__ empty_scalar,
                 float* __restrict__ out) {
    __shared__ float srows[kBlk * kRow];

    int tid = threadIdx.x;
    int g = blockIdx.x * kBlk + tid;

    if (g <= kV) {
        float r[kRow];
#pragma unroll
        for (int c = 0; c < kRow; c++) r[c] = 0.0f;

        float sx = 1.0f, sy = 1.0f, sz = 1.0f;
        float qw = 1.0f, qx = 0.0f, qy = 0.0f, qz = 0.0f;

        if (g == kV) {
            // appended "empty" gaussian row
            r[0] = 0.0f; r[1] = 0.0f; r[2] = 2.2f;
            r[3] = 1.0f;                       // opacity
            r[4 + 17] = empty_scalar[0];       // EMPTY_LABEL semantic
            sx = 100.0f; sy = 100.0f; sz = 8.0f;
        } else {
            unsigned long long key = g_keys[g];
            if (key != 0ull) {
                int idx = (int)(0xFFFFFFFFu - (unsigned)(key & 0xFFFFFFFFull));
                r[0] = means[3 * idx + 0];
                r[1] = means[3 * idx + 1];
                r[2] = means[3 * idx + 2];
                r[3] = opac[idx];
#pragma unroll
                for (int c = 0; c < 17; c++) r[4 + c] = feats[17 * idx + c];
                sx = scales[3 * idx + 0];
                sy = scales[3 * idx + 1];
                sz = scales[3 * idx + 2];
                qw = rots[4 * idx + 0];
                qx = rots[4 * idx + 1];
                qy = rots[4 * idx + 2];
                qz = rots[4 * idx + 3];
            }
            // invalid voxel: defaults -> covinv = I, rest 0 (matches ref).
        }

        float nrm = sqrtf(qw * qw + qx * qx + qy * qy + qz * qz);
        float inv = 1.0f / nrm;
        qw *= inv; qx *= inv; qy *= inv; qz *= inv;

        float r00 = 1.0f - 2.0f * (qy * qy + qz * qz);
        float r01 = 2.0f * (qx * qy - qw * qz);
        float r02 = 2.0f * (qx * qz + qw * qy);
        float r10 = 2.0f * (qx * qy + qw * qz);
        float r11 = 1.0f - 2.0f * (qx * qx + qz * qz);
        float r12 = 2.0f * (qy * qz - qw * qx);
        float r20 = 2.0f * (qx * qz - qw * qy);
        float r21 = 2.0f * (qy * qz + qw * qx);
        float r22 = 1.0f - 2.0f * (qx * qx + qy * qy);

        // cov = R^T S^2 R  =>  cov_inv = R^T S^-2 R (analytic, symmetric)
        float a0 = 1.0f / (sx * sx);
        float a1 = 1.0f / (sy * sy);
        float a2 = 1.0f / (sz * sz);

        float c00 = r00 * r00 * a0 + r10 * r10 * a1 + r20 * r20 * a2;
        float c01 = r00 * r01 * a0 + r10 * r11 * a1 + r20 * r21 * a2;
        float c02 = r00 * r02 * a0 + r10 * r12 * a1 + r20 * r22 * a2;
        float c11 = r01 * r01 * a0 + r11 * r11 * a1 + r21 * r21 * a2;
        float c12 = r01 * r02 * a0 + r11 * r12 * a1 + r21 * r22 * a2;
        float c22 = r02 * r02 * a0 + r12 * r12 * a1 + r22 * r22 * a2;

        r[22] = c00; r[23] = c01; r[24] = c02;
        r[25] = c01; r[26] = c11; r[27] = c12;
        r[28] = c02; r[29] = c12; r[30] = c22;

        // stage row in smem: address tid*31 + c, stride 31 mod 32 -> no
        // bank conflicts across the warp for any fixed c.
#pragma unroll
        for (int c = 0; c < kRow; c++) srows[tid * kRow + c] = r[c];
    }

    __syncthreads();

    // coalesced writeback (the single delta vs round 3): full blocks cover
    // a contiguous span of kBlk*31 floats, 16B-aligned -> float4 path.
    int base = blockIdx.x * kBlk;
    int nrows = min(kBlk, kV + 1 - base);
    if (nrows <= 0) return;

    if (nrows == kBlk) {
        constexpr int kVec = kBlk * kRow / 4;   // 1984 float4s
        float4* po = reinterpret_cast<float4*>(out + (size_t)base * kRow);
        const float4* ps = reinterpret_cast<const float4*>(srows);
        for (int e = tid; e < kVec; e += kBlk) {
            po[e] = ps[e];
        }
    } else {
        int nelem = nrows * kRow;
        float* po = out + (size_t)base * kRow;
        for (int e = tid; e < nelem; e += kBlk) {
            po[e] = srows[e];
        }
    }
}

extern "C" void kernel_launch(void* const* d_in, const int* in_sizes, int n_in,
                              void* d_out, int out_size) {
    const float* means        = (const float*)d_in[0];  // [N,3]
    const float* opac         = (const float*)d_in[1];  // [N,1]
    const float* feats        = (const float*)d_in[2];  // [N,17]
    const float* scales       = (const float*)d_in[3];  // [N,3]
    const float* rots         = (const float*)d_in[4];  // [N,4]
    const float* empty_scalar = (const float*)d_in[5];  // [1]
    float* out = (float*)d_out;                         // [1, V+1, 31]

    int n = in_sizes[0] / 3;

    gv_init_kernel<<<(kV / 2 + 255) / 256, 256>>>();
    gv_scatter_kernel<<<(n + 255) / 256, 256>>>(means, opac, n);
    gv_output_kernel<<<(kV + 1 + kBlk - 1) / kBlk, kBlk>>>(
        means, opac, feats, scales, rots, empty_scalar, out);
}